// round 2
// baseline (speedup 1.0000x reference)
#include <cuda_runtime.h>
#include <cstddef>

// ----- problem dims -----
constexpr int NB = 16;        // batch
constexpr int NC = 512;       // channels / embed dim
constexpr int NHEADS = 8;
constexpr int HD = 64;        // head dim
constexpr int FF = 2048;
constexpr int LAYERS = 6;
constexpr int T = 1280;       // tokens
constexpr int MROWS = NB * T; // 20480

// ----- scratch (static device arrays; no allocation allowed) -----
__device__ float g_x [(size_t)MROWS * NC];
__device__ float g_h [(size_t)MROWS * NC];
__device__ float g_q [(size_t)MROWS * NC];
__device__ float g_k [(size_t)MROWS * NC];
__device__ float g_v [(size_t)MROWS * NC];
__device__ float g_y [(size_t)MROWS * NC];
__device__ float g_ff[(size_t)MROWS * FF];
__device__ float g_s [(size_t)NB * NHEADS * T * T];

// ============================================================
// Embedding: x[b,t,c] = pos[t,c] + (image|radar)[b,c,h,w]
// ============================================================
__global__ void embed_kernel(const float* __restrict__ img,
                             const float* __restrict__ rad,
                             const float* __restrict__ pos,
                             float* __restrict__ x) {
    int idx = blockIdx.x * 256 + threadIdx.x;   // < MROWS*NC
    int c = idx & (NC - 1);
    int r = idx >> 9;          // /512
    int b = r / T;
    int t = r - b * T;
    float val;
    if (t < 1024) {
        int hh = t >> 6, ww = t & 63;
        val = img[(((size_t)b * NC + c) * 16 + hh) * 64 + ww];
    } else {
        int tr = t - 1024;
        int hh = tr >> 4, ww = tr & 15;
        val = rad[(((size_t)b * NC + c) * 16 + hh) * 16 + ww];
    }
    x[idx] = pos[t * NC + c] + val;
}

// ============================================================
// LayerNorm over C=512 (one block of 128 threads per row)
// ============================================================
__global__ void ln_kernel(const float* __restrict__ x, float* __restrict__ o,
                          const float* __restrict__ w, const float* __restrict__ bsh) {
    int r = blockIdx.x, tid = threadIdx.x;
    const float4 v = *(const float4*)(x + (size_t)r * NC + tid * 4);
    float s  = v.x + v.y + v.z + v.w;
    float sq = v.x * v.x + v.y * v.y + v.z * v.z + v.w * v.w;
    #pragma unroll
    for (int off = 16; off; off >>= 1) {
        s  += __shfl_xor_sync(0xFFFFFFFFu, s,  off);
        sq += __shfl_xor_sync(0xFFFFFFFFu, sq, off);
    }
    __shared__ float ss[4], sqs[4];
    if ((tid & 31) == 0) { ss[tid >> 5] = s; sqs[tid >> 5] = sq; }
    __syncthreads();
    s  = ss[0] + ss[1] + ss[2] + ss[3];
    sq = sqs[0] + sqs[1] + sqs[2] + sqs[3];
    float mean = s * (1.0f / NC);
    float var  = sq * (1.0f / NC) - mean * mean;
    float rstd = rsqrtf(var + 1e-5f);
    float4 wv = *(const float4*)(w + tid * 4);
    float4 bv = *(const float4*)(bsh + tid * 4);
    float4 ov;
    ov.x = (v.x - mean) * rstd * wv.x + bv.x;
    ov.y = (v.y - mean) * rstd * wv.y + bv.y;
    ov.z = (v.z - mean) * rstd * wv.z + bv.z;
    ov.w = (v.w - mean) * rstd * wv.w + bv.w;
    *(float4*)(o + (size_t)r * NC + tid * 4) = ov;
}

// ============================================================
// Final LN fused with output layout:
//   t<1024 -> out[b*1024*C + t*C], else out[B*1024*C + b*256*C + (t-1024)*C]
// ============================================================
__global__ void lnf_out_kernel(const float* __restrict__ x, float* __restrict__ out,
                               const float* __restrict__ w, const float* __restrict__ bsh) {
    int r = blockIdx.x, tid = threadIdx.x;
    int b = r / T, t = r - b * T;
    const float4 v = *(const float4*)(x + (size_t)r * NC + tid * 4);
    float s  = v.x + v.y + v.z + v.w;
    float sq = v.x * v.x + v.y * v.y + v.z * v.z + v.w * v.w;
    #pragma unroll
    for (int off = 16; off; off >>= 1) {
        s  += __shfl_xor_sync(0xFFFFFFFFu, s,  off);
        sq += __shfl_xor_sync(0xFFFFFFFFu, sq, off);
    }
    __shared__ float ss[4], sqs[4];
    if ((tid & 31) == 0) { ss[tid >> 5] = s; sqs[tid >> 5] = sq; }
    __syncthreads();
    s  = ss[0] + ss[1] + ss[2] + ss[3];
    sq = sqs[0] + sqs[1] + sqs[2] + sqs[3];
    float mean = s * (1.0f / NC);
    float var  = sq * (1.0f / NC) - mean * mean;
    float rstd = rsqrtf(var + 1e-5f);
    float4 wv = *(const float4*)(w + tid * 4);
    float4 bv = *(const float4*)(bsh + tid * 4);
    float4 ov;
    ov.x = (v.x - mean) * rstd * wv.x + bv.x;
    ov.y = (v.y - mean) * rstd * wv.y + bv.y;
    ov.z = (v.z - mean) * rstd * wv.z + bv.z;
    ov.w = (v.w - mean) * rstd * wv.w + bv.w;
    float* dst;
    if (t < 1024) dst = out + ((size_t)b * 1024 + t) * NC;
    else          dst = out + (size_t)NB * 1024 * NC + ((size_t)b * 256 + (t - 1024)) * NC;
    *(float4*)(dst + tid * 4) = ov;
}

// ============================================================
// Generic GEMM: D = epi(A[MxK] @ Bw[KxN] + bias [+ res])
// 128x128 tile, BK=16, 256 threads, 8x8 per thread.
// EPI: 0 = bias, 1 = bias+relu, 2 = bias+residual
// M%128==0, N%128==0, K%16==0 guaranteed by problem dims.
// ============================================================
template <int EPI>
__global__ void __launch_bounds__(256)
gemm_kernel(const float* __restrict__ A, const float* __restrict__ Bw,
            const float* __restrict__ bias, const float* __restrict__ res,
            float* __restrict__ D, int M, int N, int K) {
    __shared__ float As[16][128];
    __shared__ float Bs[16][128];
    int tid = threadIdx.x;
    int bm = blockIdx.y * 128;
    int bn = blockIdx.x * 128;
    int tx = tid & 15, ty = tid >> 4;

    int arow = tid >> 1;
    int acol = (tid & 1) * 8;
    int brow = tid >> 4;
    int bcol = (tid & 15) * 8;
    const float* Aptr = A  + (size_t)(bm + arow) * K + acol;
    const float* Bptr = Bw + (size_t)brow * N + bn + bcol;

    float acc[8][8];
    #pragma unroll
    for (int i = 0; i < 8; i++)
        #pragma unroll
        for (int j = 0; j < 8; j++) acc[i][j] = 0.0f;

    for (int k0 = 0; k0 < K; k0 += 16) {
        float4 a0 = *(const float4*)(Aptr);
        float4 a1 = *(const float4*)(Aptr + 4);
        float4 b0 = *(const float4*)(Bptr);
        float4 b1 = *(const float4*)(Bptr + 4);
        Aptr += 16;
        Bptr += (size_t)16 * N;
        As[acol + 0][arow] = a0.x; As[acol + 1][arow] = a0.y;
        As[acol + 2][arow] = a0.z; As[acol + 3][arow] = a0.w;
        As[acol + 4][arow] = a1.x; As[acol + 5][arow] = a1.y;
        As[acol + 6][arow] = a1.z; As[acol + 7][arow] = a1.w;
        *(float4*)&Bs[brow][bcol]     = b0;
        *(float4*)&Bs[brow][bcol + 4] = b1;
        __syncthreads();
        #pragma unroll
        for (int k = 0; k < 16; k++) {
            float a[8], bb[8];
            *(float4*)(a)      = *(const float4*)&As[k][ty * 8];
            *(float4*)(a + 4)  = *(const float4*)&As[k][ty * 8 + 4];
            *(float4*)(bb)     = *(const float4*)&Bs[k][tx * 8];
            *(float4*)(bb + 4) = *(const float4*)&Bs[k][tx * 8 + 4];
            #pragma unroll
            for (int i = 0; i < 8; i++)
                #pragma unroll
                for (int j = 0; j < 8; j++)
                    acc[i][j] = fmaf(a[i], bb[j], acc[i][j]);
        }
        __syncthreads();
    }

    float bvals[8];
    #pragma unroll
    for (int j = 0; j < 8; j++) bvals[j] = bias[bn + tx * 8 + j];
    #pragma unroll
    for (int i = 0; i < 8; i++) {
        int m = bm + ty * 8 + i;
        float* drow = D + (size_t)m * N + bn + tx * 8;
        #pragma unroll
        for (int j = 0; j < 8; j++) {
            float vv = acc[i][j] + bvals[j];
            if (EPI == 1) vv = fmaxf(vv, 0.0f);
            if (EPI == 2) vv += drow[j];   // residual: res aliases D (per-element RMW)
            drow[j] = vv;
        }
    }
}

// ============================================================
// Attention scores: S[bh, t, s] = 0.125 * sum_d Q[t,d]*K[s,d]
// One block per (64x64) tile of one (b,h). K=64 in one shot.
// ============================================================
__global__ void __launch_bounds__(256)
scores_kernel(const float* __restrict__ q, const float* __restrict__ k,
              float* __restrict__ S) {
    int bh = blockIdx.z;
    int b = bh >> 3, nh = bh & 7;
    int t0 = blockIdx.y * 64, s0 = blockIdx.x * 64;
    const float* qb = q + ((size_t)b * T) * NC + nh * HD;
    const float* kb = k + ((size_t)b * T) * NC + nh * HD;
    __shared__ float Qs[64][68];   // [d][t]
    __shared__ float Ks[64][68];   // [d][s]
    int tid = threadIdx.x;
    int lr = tid >> 2, lc = (tid & 3) * 16;
    const float* qs = qb + (size_t)(t0 + lr) * NC + lc;
    const float* ks = kb + (size_t)(s0 + lr) * NC + lc;
    #pragma unroll
    for (int u = 0; u < 16; u += 4) {
        float4 qv = *(const float4*)(qs + u);
        float4 kv = *(const float4*)(ks + u);
        Qs[lc + u + 0][lr] = qv.x; Qs[lc + u + 1][lr] = qv.y;
        Qs[lc + u + 2][lr] = qv.z; Qs[lc + u + 3][lr] = qv.w;
        Ks[lc + u + 0][lr] = kv.x; Ks[lc + u + 1][lr] = kv.y;
        Ks[lc + u + 2][lr] = kv.z; Ks[lc + u + 3][lr] = kv.w;
    }
    __syncthreads();
    int tx = tid & 15, ty = tid >> 4;
    float acc[4][4];
    #pragma unroll
    for (int i = 0; i < 4; i++)
        #pragma unroll
        for (int j = 0; j < 4; j++) acc[i][j] = 0.0f;
    #pragma unroll 16
    for (int d = 0; d < 64; d++) {
        float qa[4], ka[4];
        *(float4*)qa = *(const float4*)&Qs[d][ty * 4];
        *(float4*)ka = *(const float4*)&Ks[d][tx * 4];
        #pragma unroll
        for (int i = 0; i < 4; i++)
            #pragma unroll
            for (int j = 0; j < 4; j++)
                acc[i][j] = fmaf(qa[i], ka[j], acc[i][j]);
    }
    float* outp = S + ((size_t)bh * T + t0 + ty * 4) * T + s0 + tx * 4;
    #pragma unroll
    for (int i = 0; i < 4; i++) {
        float4 ov = make_float4(acc[i][0] * 0.125f, acc[i][1] * 0.125f,
                                acc[i][2] * 0.125f, acc[i][3] * 0.125f);
        *(float4*)(outp + (size_t)i * T) = ov;
    }
}

// ============================================================
// Row softmax over T=1280 (256 threads, 5 elems/thread)
// ============================================================
__global__ void softmax_kernel(float* __restrict__ S) {
    size_t row = blockIdx.x;
    float* p = S + row * (size_t)T;
    int tid = threadIdx.x;
    float vals[5];
    float mx = -1e30f;
    #pragma unroll
    for (int u = 0; u < 5; u++) { vals[u] = p[tid + u * 256]; mx = fmaxf(mx, vals[u]); }
    #pragma unroll
    for (int off = 16; off; off >>= 1) mx = fmaxf(mx, __shfl_xor_sync(0xFFFFFFFFu, mx, off));
    __shared__ float sm[8], sm2[8];
    if ((tid & 31) == 0) sm[tid >> 5] = mx;
    __syncthreads();
    float bm = sm[0];
    #pragma unroll
    for (int w = 1; w < 8; w++) bm = fmaxf(bm, sm[w]);
    float ssum = 0.0f;
    #pragma unroll
    for (int u = 0; u < 5; u++) { vals[u] = __expf(vals[u] - bm); ssum += vals[u]; }
    #pragma unroll
    for (int off = 16; off; off >>= 1) ssum += __shfl_xor_sync(0xFFFFFFFFu, ssum, off);
    if ((tid & 31) == 0) sm2[tid >> 5] = ssum;
    __syncthreads();
    float tot = sm2[0];
    #pragma unroll
    for (int w = 1; w < 8; w++) tot += sm2[w];
    float inv = 1.0f / tot;
    #pragma unroll
    for (int u = 0; u < 5; u++) p[tid + u * 256] = vals[u] * inv;
}

// ============================================================
// AV: Y[t,d] = sum_s P[t,s] * V[s,d]   (per (b,h); HD=64 full tile)
// ============================================================
__global__ void __launch_bounds__(256)
av_kernel(const float* __restrict__ S, const float* __restrict__ v,
          float* __restrict__ y) {
    int bh = blockIdx.y;
    int b = bh >> 3, nh = bh & 7;
    int t0 = blockIdx.x * 64;
    __shared__ float Ps[64][68];   // [s][t]
    __shared__ float Vs[64][64];   // [s][d]
    int tid = threadIdx.x;
    int tx = tid & 15, ty = tid >> 4;
    int lr = tid >> 2, lc = (tid & 3) * 16;
    const float* sbase = S + ((size_t)bh * T + t0 + lr) * T + lc;
    const float* vb = v + ((size_t)b * T) * NC + nh * HD;
    float acc[4][4];
    #pragma unroll
    for (int i = 0; i < 4; i++)
        #pragma unroll
        for (int j = 0; j < 4; j++) acc[i][j] = 0.0f;

    for (int s0 = 0; s0 < T; s0 += 64) {
        #pragma unroll
        for (int u = 0; u < 16; u += 4) {
            float4 pv = *(const float4*)(sbase + s0 + u);
            Ps[lc + u + 0][lr] = pv.x; Ps[lc + u + 1][lr] = pv.y;
            Ps[lc + u + 2][lr] = pv.z; Ps[lc + u + 3][lr] = pv.w;
            float4 vv = *(const float4*)(vb + (size_t)(s0 + lr) * NC + lc + u);
            *(float4*)&Vs[lr][lc + u] = vv;
        }
        __syncthreads();
        #pragma unroll 16
        for (int s = 0; s < 64; s++) {
            float pa[4], va[4];
            *(float4*)pa = *(const float4*)&Ps[s][ty * 4];
            *(float4*)va = *(const float4*)&Vs[s][tx * 4];
            #pragma unroll
            for (int i = 0; i < 4; i++)
                #pragma unroll
                for (int j = 0; j < 4; j++)
                    acc[i][j] = fmaf(pa[i], va[j], acc[i][j]);
        }
        __syncthreads();
    }
    #pragma unroll
    for (int i = 0; i < 4; i++) {
        float* dst = y + ((size_t)b * T + t0 + ty * 4 + i) * NC + nh * HD + tx * 4;
        *(float4*)dst = make_float4(acc[i][0], acc[i][1], acc[i][2], acc[i][3]);
    }
}

// ============================================================
// host launch
// ============================================================
extern "C" void kernel_launch(void* const* d_in, const int* in_sizes, int n_in,
                              void* d_out, int out_size) {
    const float* img  = (const float*)d_in[0];
    const float* rad  = (const float*)d_in[1];
    const float* pos  = (const float*)d_in[2];
    const float* ln1w = (const float*)d_in[3];
    const float* ln1b = (const float*)d_in[4];
    const float* Wq   = (const float*)d_in[5];
    const float* bq   = (const float*)d_in[6];
    const float* Wk   = (const float*)d_in[7];
    const float* bk   = (const float*)d_in[8];
    const float* Wv   = (const float*)d_in[9];
    const float* bv   = (const float*)d_in[10];
    const float* Wo   = (const float*)d_in[11];
    const float* bo   = (const float*)d_in[12];
    const float* ln2w = (const float*)d_in[13];
    const float* ln2b = (const float*)d_in[14];
    const float* W1   = (const float*)d_in[15];
    const float* b1   = (const float*)d_in[16];
    const float* W2   = (const float*)d_in[17];
    const float* b2   = (const float*)d_in[18];
    const float* lnfw = (const float*)d_in[19];
    const float* lnfb = (const float*)d_in[20];
    float* out = (float*)d_out;

    float *x, *h, *q, *k, *v, *y, *ff, *s;
    cudaGetSymbolAddress((void**)&x,  g_x);
    cudaGetSymbolAddress((void**)&h,  g_h);
    cudaGetSymbolAddress((void**)&q,  g_q);
    cudaGetSymbolAddress((void**)&k,  g_k);
    cudaGetSymbolAddress((void**)&v,  g_v);
    cudaGetSymbolAddress((void**)&y,  g_y);
    cudaGetSymbolAddress((void**)&ff, g_ff);
    cudaGetSymbolAddress((void**)&s,  g_s);

    embed_kernel<<<(MROWS * NC) / 256, 256>>>(img, rad, pos, x);

    dim3 gC(NC / 128, MROWS / 128);     // (4, 160)
    dim3 gF(FF / 128, MROWS / 128);     // (16, 160)
    dim3 gSc(T / 64, T / 64, NB * NHEADS);  // (20, 20, 128)
    dim3 gAv(T / 64, NB * NHEADS);          // (20, 128)

    for (int i = 0; i < LAYERS; i++) {
        size_t wOff = (size_t)i * NC * NC;
        ln_kernel<<<MROWS, 128>>>(x, h, ln1w + i * NC, ln1b + i * NC);
        gemm_kernel<0><<<gC, 256>>>(h, Wq + wOff, bq + i * NC, nullptr, q, MROWS, NC, NC);
        gemm_kernel<0><<<gC, 256>>>(h, Wk + wOff, bk + i * NC, nullptr, k, MROWS, NC, NC);
        gemm_kernel<0><<<gC, 256>>>(h, Wv + wOff, bv + i * NC, nullptr, v, MROWS, NC, NC);
        scores_kernel<<<gSc, 256>>>(q, k, s);
        softmax_kernel<<<NB * NHEADS * T, 256>>>(s);
        av_kernel<<<gAv, 256>>>(s, v, y);
        gemm_kernel<2><<<gC, 256>>>(y, Wo + wOff, bo + i * NC, x, x, MROWS, NC, NC);
        ln_kernel<<<MROWS, 128>>>(x, h, ln2w + i * NC, ln2b + i * NC);
        gemm_kernel<1><<<gF, 256>>>(h, W1 + (size_t)i * NC * FF, b1 + i * FF, nullptr,
                                    ff, MROWS, FF, NC);
        gemm_kernel<2><<<gC, 256>>>(ff, W2 + (size_t)i * FF * NC, b2 + i * NC, x, x,
                                    MROWS, NC, FF);
    }
    lnf_out_kernel<<<MROWS, 128>>>(x, out, lnfw, lnfb);
}